// round 4
// baseline (speedup 1.0000x reference)
#include <cuda_runtime.h>

// Equivariant linear via block-diagonal GEMMs on tensor cores (3xTF32).
// Blocks (mul, d, x_off, w_off):
//   (256, 1,   0,     0)  (128, 3, 256, 65536)  (64, 5, 640, 81920)  (32, 7, 960, 86016)
// y[b, XO + v*D + i] = (1/sqrt(MUL)) * sum_u w[WO + v*MUL + u] * x[b, XO + u*D + i]
// GEMM view per block: M=MUL (v), K=MUL (u), N=BATCH*D (n = b*D+i).

#define FEAT 1184
#define BATCH_N 131072
#define NT 256

__device__ __forceinline__ float tf32r(float v) {
    float r; asm("cvt.rna.tf32.f32 %0, %1;" : "=f"(r) : "f"(v)); return r;
}

// D += A(16x8,row) * B(8x8,col), tf32 inputs, fp32 accum.
__device__ __forceinline__ void mma8(float* d, const unsigned* a, const unsigned* b) {
    asm volatile("mma.sync.aligned.m16n8k8.row.col.f32.tf32.tf32.f32 "
        "{%0,%1,%2,%3}, {%4,%5,%6,%7}, {%8,%9}, {%0,%1,%2,%3};"
        : "+f"(d[0]), "+f"(d[1]), "+f"(d[2]), "+f"(d[3])
        : "r"(a[0]), "r"(a[1]), "r"(a[2]), "r"(a[3]), "r"(b[0]), "r"(b[1]));
}

template<int MUL, int D, int XO, int WO, int MCTA, int NB, int WM, int WN>
__global__ __launch_bounds__(NT, 2)
void eqlin_mma(const float* __restrict__ x, const float* __restrict__ w,
               float* __restrict__ y)
{
    constexpr int KC   = 16;                 // K chunk (u)
    constexpr int NCH  = MUL / KC;
    constexpr int NCOL = NB * D;             // CTA n-columns
    constexpr int WSS  = KC + 4;             // W smem row stride (conflict-free A frags)
    constexpr int NS   = NCOL + 8;           // X smem row stride (conflict-free B frags)
    constexpr int TMW  = MCTA / WM;          // warp m tile
    constexpr int TNW  = NCOL / WN;          // warp n tile
    constexpr int MF   = TMW / 16;
    constexpr int NF   = TNW / 8;
    static_assert(TMW % 16 == 0 && TNW % 8 == 0, "warp tile");
    static_assert(WM * WN * 32 == NT, "warp grid");
    constexpr int SN    = (MCTA * (NCOL + 2) * 4 <= 49152) ? (NCOL + 2) : NCOL;
    constexpr int LOADB = (MCTA * WSS * 2 + KC * NS * 2) * 4;
    constexpr int EPIB  = MCTA * SN * 4;
    constexpr int SMB   = LOADB > EPIB ? LOADB : EPIB;
    static_assert(SMB <= 49152, "smem");
    static_assert((NB * KC * D) % NT == 0 && (MCTA * KC) % NT == 0, "loader");
    static_assert((NB * MCTA * D) % (4 * NT) == 0, "epilogue");

    __shared__ __align__(16) char smembuf[SMB];
    float* wsh = (float*)smembuf;            // [MCTA][WSS] hi
    float* wsl = wsh + MCTA * WSS;           // lo
    float* xsh = wsl + MCTA * WSS;           // [KC][NS] hi
    float* xsl = xsh + KC * NS;              // lo
    float* S   = (float*)smembuf;            // epilogue [MCTA][SN]

    const int tid = threadIdx.x;
    const int b0  = blockIdx.x * NB;
    const int v0  = blockIdx.y * MCTA;
    const int wid = tid >> 5, lane = tid & 31;
    const int g = lane >> 2, tg = lane & 3;
    const int wm = wid % WM, wn = wid / WM;
    const int mb0 = wm * TMW, nb0 = wn * TNW;
    const float c = rsqrtf((float)MUL);

    float acc[MF][NF][4];
    #pragma unroll
    for (int mf = 0; mf < MF; ++mf)
        #pragma unroll
        for (int nf = 0; nf < NF; ++nf)
            #pragma unroll
            for (int q = 0; q < 4; ++q) acc[mf][nf][q] = 0.f;

    for (int ch = 0; ch < NCH; ++ch) {
        const int u0 = ch * KC;
        __syncthreads();

        // ---- stage X chunk, transposed to [u][n], split hi/lo
        #pragma unroll
        for (int t = 0; t < NB * KC * D / NT; ++t) {
            int f = tid + t * NT;
            int bl = f / (KC * D), r = f % (KC * D);   // r = (u_local, i) flat
            float v = x[(size_t)(b0 + bl) * FEAT + XO + u0 * D + r];
            float h = tf32r(v), l = tf32r(v - h);
            int ul = r / D, il = r % D;
            xsh[ul * NS + bl * D + il] = h;
            xsl[ul * NS + bl * D + il] = l;
        }
        // ---- stage W chunk [m][k], pre-scaled, split hi/lo
        #pragma unroll
        for (int t = 0; t < MCTA * KC / NT; ++t) {
            int f = tid + t * NT;
            int m = f / KC, k = f % KC;
            float v = w[WO + (size_t)(v0 + m) * MUL + u0 + k] * c;
            float h = tf32r(v), l = tf32r(v - h);
            wsh[m * WSS + k] = h;
            wsl[m * WSS + k] = l;
        }
        __syncthreads();

        const unsigned* WH = (const unsigned*)wsh;
        const unsigned* WL = (const unsigned*)wsl;
        const unsigned* XH = (const unsigned*)xsh;
        const unsigned* XL = (const unsigned*)xsl;

        #pragma unroll
        for (int k8 = 0; k8 < KC / 8; ++k8) {
            const int kk = k8 * 8;
            unsigned ah[MF][4], al[MF][4], bh[NF][2], bl2[NF][2];
            #pragma unroll
            for (int mf = 0; mf < MF; ++mf) {
                int mb = mb0 + mf * 16;
                ah[mf][0] = WH[(mb + g) * WSS + kk + tg];
                ah[mf][1] = WH[(mb + g + 8) * WSS + kk + tg];
                ah[mf][2] = WH[(mb + g) * WSS + kk + tg + 4];
                ah[mf][3] = WH[(mb + g + 8) * WSS + kk + tg + 4];
                al[mf][0] = WL[(mb + g) * WSS + kk + tg];
                al[mf][1] = WL[(mb + g + 8) * WSS + kk + tg];
                al[mf][2] = WL[(mb + g) * WSS + kk + tg + 4];
                al[mf][3] = WL[(mb + g + 8) * WSS + kk + tg + 4];
            }
            #pragma unroll
            for (int nf = 0; nf < NF; ++nf) {
                int nn = nb0 + nf * 8 + g;
                bh[nf][0]  = XH[(kk + tg) * NS + nn];
                bh[nf][1]  = XH[(kk + tg + 4) * NS + nn];
                bl2[nf][0] = XL[(kk + tg) * NS + nn];
                bl2[nf][1] = XL[(kk + tg + 4) * NS + nn];
            }
            #pragma unroll
            for (int mf = 0; mf < MF; ++mf)
                #pragma unroll
                for (int nf = 0; nf < NF; ++nf) {
                    mma8(acc[mf][nf], ah[mf], bh[nf]);   // hi*hi
                    mma8(acc[mf][nf], ah[mf], bl2[nf]);  // hi*lo
                    mma8(acc[mf][nf], al[mf], bh[nf]);   // lo*hi
                }
        }
    }

    // ---- epilogue: fragments -> smem [m][n] -> coalesced float4 stores
    __syncthreads();
    #pragma unroll
    for (int mf = 0; mf < MF; ++mf)
        #pragma unroll
        for (int nf = 0; nf < NF; ++nf) {
            int mb = mb0 + mf * 16, nn = nb0 + nf * 8 + 2 * tg;
            S[(mb + g) * SN + nn]     = acc[mf][nf][0];
            S[(mb + g) * SN + nn + 1] = acc[mf][nf][1];
            S[(mb + g + 8) * SN + nn]     = acc[mf][nf][2];
            S[(mb + g + 8) * SN + nn + 1] = acc[mf][nf][3];
        }
    __syncthreads();

    constexpr int ROW = MCTA * D;   // contiguous output span per batch row
    #pragma unroll
    for (int t = 0; t < NB * ROW / 4 / NT; ++t) {
        int f4 = (tid + t * NT) * 4;
        int bl = f4 / ROW, r = f4 % ROW;
        float4 o;
        o.x = S[((r + 0) / D) * SN + bl * D + (r + 0) % D];
        o.y = S[((r + 1) / D) * SN + bl * D + (r + 1) % D];
        o.z = S[((r + 2) / D) * SN + bl * D + (r + 2) % D];
        o.w = S[((r + 3) / D) * SN + bl * D + (r + 3) % D];
        *(float4*)(y + (size_t)(b0 + bl) * FEAT + XO + v0 * D + r) = o;
    }
}

extern "C" void kernel_launch(void* const* d_in, const int* in_sizes, int n_in,
                              void* d_out, int out_size) {
    const float* x = (const float*)d_in[0];
    const float* w = (const float*)d_in[1];
    float* y = (float*)d_out;
    (void)in_sizes; (void)n_in; (void)out_size;

    //        MUL  D   XO    WO   MCTA NB WM WN
    eqlin_mma<256, 1,   0,     0, 128, 64, 4, 2><<<dim3(BATCH_N / 64, 2), NT>>>(x, w, y);
    eqlin_mma<128, 3, 256, 65536, 128, 32, 4, 2><<<dim3(BATCH_N / 32, 1), NT>>>(x, w, y);
    eqlin_mma< 64, 5, 640, 81920,  64, 32, 2, 4><<<dim3(BATCH_N / 32, 1), NT>>>(x, w, y);
    eqlin_mma< 32, 7, 960, 86016,  32, 32, 2, 4><<<dim3(BATCH_N / 32, 1), NT>>>(x, w, y);
}

// round 5
// speedup vs baseline: 1.5342x; 1.5342x over previous
#include <cuda_runtime.h>
#include <stdint.h>

// Equivariant linear via block-diagonal GEMMs on tensor cores (2-term TF32 split).
// Blocks (mul, d, x_off, w_off):
//   (256, 1,   0,     0)  (128, 3, 256, 65536)  (64, 5, 640, 81920)  (32, 7, 960, 86016)
// y[b, XO + v*D + i] = (1/sqrt(MUL)) * sum_u w[WO + v*MUL + u] * x[b, XO + u*D + i]
// GEMM per block: M=MUL (v), K=MUL (u), N=BATCH*D (n = b*D+i).
// w pre-split (hi,lo interleaved, pre-scaled) into a device global by a tiny
// precompute kernel; main kernels fetch W tiles with cp.async and compute
// acc += wh*xh + wl*xh  (x single-rounded tf32; w exact to fp32).

#define FEAT 1184
#define BATCH_N 131072
#define NT 256
#define W_DIM 87040

__device__ float g_wsplit[2 * W_DIM];

__device__ __forceinline__ float tf32r(float v) {
    float r; asm("cvt.rna.tf32.f32 %0, %1;" : "=f"(r) : "f"(v)); return r;
}
__device__ __forceinline__ unsigned fu(float v) { return __float_as_uint(v); }

__device__ __forceinline__ void cp16(uint32_t saddr, const void* gaddr) {
    asm volatile("cp.async.ca.shared.global [%0], [%1], 16;" :: "r"(saddr), "l"(gaddr));
}

// D += A(16x8,row) * B(8x8,col), tf32 inputs, fp32 accum.
__device__ __forceinline__ void mma8(float* d, const unsigned* a, const unsigned* b) {
    asm volatile("mma.sync.aligned.m16n8k8.row.col.f32.tf32.tf32.f32 "
        "{%0,%1,%2,%3}, {%4,%5,%6,%7}, {%8,%9}, {%0,%1,%2,%3};"
        : "+f"(d[0]), "+f"(d[1]), "+f"(d[2]), "+f"(d[3])
        : "r"(a[0]), "r"(a[1]), "r"(a[2]), "r"(a[3]), "r"(b[0]), "r"(b[1]));
}

__global__ void wsplit_kernel(const float* __restrict__ w) {
    int idx = blockIdx.x * NT + threadIdx.x;
    if (idx >= W_DIM) return;
    float c = (idx < 65536) ? 0.0625f
            : (idx < 81920) ? 0.08838834764831845f
            : (idx < 86016) ? 0.125f
                            : 0.17677669529663687f;
    float v = w[idx] * c;
    float h = tf32r(v);
    g_wsplit[2 * idx]     = h;
    g_wsplit[2 * idx + 1] = tf32r(v - h);
}

template<int MUL, int D, int XO, int WO, int MCTA, int NB, int KC, int WM, int WN>
__global__ __launch_bounds__(NT, 2)
void eqlin_mma(const float* __restrict__ x, float* __restrict__ y)
{
    constexpr int NCOL = NB * D;
    constexpr int NCH  = MUL / KC;
    constexpr int S2   = 2 * KC + 8;        // W smem stride (floats), (hi,lo) interleaved
    constexpr bool RM  = (D == 1);          // x smem row-major [n][k]
    constexpr int KS   = KC + 4;            // x stride (RM) — conflict-free B-frag LDS
    constexpr int NS   = NCOL + 9;          // x stride (KN) — conflict-free STS
    constexpr int TMW  = MCTA / WM;
    constexpr int TNW  = NCOL / WN;
    constexpr int MF   = TMW / 16;
    constexpr int NF   = TNW / 8;
    static_assert(TMW % 16 == 0 && TNW % 8 == 0 && WM * WN * 32 == NT, "tiling");

    constexpr int WB = MCTA * S2 * 4;
    constexpr int XB = RM ? NB * KS * 4 : KC * NS * 4;
    constexpr int SN = NCOL + 2;
    constexpr int EPIB = RM ? 0 : MCTA * SN * 4;
    constexpr int SMB = (WB + XB) > EPIB ? (WB + XB) : EPIB;
    static_assert(SMB <= 49152, "smem");
    constexpr int SEGROW = KC / 2;                     // 16B segs per W row
    static_assert((MCTA * SEGROW) % NT == 0, "w loader");
    static_assert(RM ? ((NB * KC / 4) % NT == 0) : ((NB * KC) % NT == 0), "x loader");
    static_assert(RM || (NB * MCTA * D) % (4 * NT) == 0, "epilogue");

    __shared__ __align__(16) char smembuf[SMB];
    float* wsm = (float*)smembuf;                      // [MCTA][S2] interleaved (hi,lo)
    float* xs  = wsm + MCTA * S2;                      // RM: [NB][KS]  else [KC][NS]
    float* S   = (float*)smembuf;                      // epilogue (D>1)

    const int tid = threadIdx.x;
    const int b0  = blockIdx.x * NB;
    const int v0  = blockIdx.y * MCTA;
    const int wid = tid >> 5, lane = tid & 31;
    const int g = lane >> 2, tg = lane & 3;
    const int wm = wid % WM, wn = wid / WM;
    const int mb0 = wm * TMW, nb0 = wn * TNW;

    const uint32_t wsm_u32 = (uint32_t)__cvta_generic_to_shared(wsm);

    float acc[MF][NF][4];
    #pragma unroll
    for (int mf = 0; mf < MF; ++mf)
        #pragma unroll
        for (int nf = 0; nf < NF; ++nf)
            #pragma unroll
            for (int q = 0; q < 4; ++q) acc[mf][nf][q] = 0.f;

    for (int ch = 0; ch < NCH; ++ch) {
        const int u0 = ch * KC;
        __syncthreads();

        // ---- W tile via cp.async from pre-split global (16B segments)
        #pragma unroll
        for (int t = 0; t < MCTA * SEGROW / NT; ++t) {
            int sid = tid + t * NT;
            int m = sid / SEGROW, s = sid % SEGROW;
            const float* gp = g_wsplit + 2 * (WO + (size_t)(v0 + m) * MUL + u0) + s * 4;
            cp16(wsm_u32 + (uint32_t)(m * S2 + s * 4) * 4u, gp);
        }
        asm volatile("cp.async.commit_group;");

        // ---- X tile (tf32-rounded)
        if (RM) {
            #pragma unroll
            for (int t = 0; t < NB * KC / 4 / NT; ++t) {
                int f = tid + t * NT;
                int bl = f / (KC / 4), us = (f % (KC / 4)) * 4;
                const float4 v4 = *(const float4*)(x + (size_t)(b0 + bl) * FEAT
                                                   + XO + u0 + us);
                float4 o;
                o.x = tf32r(v4.x); o.y = tf32r(v4.y);
                o.z = tf32r(v4.z); o.w = tf32r(v4.w);
                *(float4*)(xs + bl * KS + us) = o;
            }
        } else {
            #pragma unroll
            for (int t = 0; t < NB * KC / NT; ++t) {
                int p = tid + t * NT;
                int bl = p / KC, ul = p % KC;
                const float* gp = x + (size_t)(b0 + bl) * FEAT + XO + (u0 + ul) * D;
                float* sp = xs + ul * NS + bl * D;
                #pragma unroll
                for (int i = 0; i < D; ++i) sp[i] = tf32r(gp[i]);
            }
        }
        asm volatile("cp.async.wait_group 0;");
        __syncthreads();

        const float2* W2 = (const float2*)wsm;

        #pragma unroll
        for (int k8 = 0; k8 < KC / 8; ++k8) {
            const int kk = k8 * 8;
            float2 aw[MF][4];
            #pragma unroll
            for (int mf = 0; mf < MF; ++mf) {
                int r0 = (mb0 + mf * 16 + g) * (S2 / 2);
                int r1 = r0 + 8 * (S2 / 2);
                aw[mf][0] = W2[r0 + kk + tg];
                aw[mf][1] = W2[r1 + kk + tg];
                aw[mf][2] = W2[r0 + kk + tg + 4];
                aw[mf][3] = W2[r1 + kk + tg + 4];
            }
            unsigned bh[NF][2];
            #pragma unroll
            for (int nf = 0; nf < NF; ++nf) {
                int nn = nb0 + nf * 8 + g;
                if (RM) {
                    bh[nf][0] = fu(xs[nn * KS + kk + tg]);
                    bh[nf][1] = fu(xs[nn * KS + kk + tg + 4]);
                } else {
                    bh[nf][0] = fu(xs[(kk + tg) * NS + nn]);
                    bh[nf][1] = fu(xs[(kk + tg + 4) * NS + nn]);
                }
            }
            #pragma unroll
            for (int mf = 0; mf < MF; ++mf) {
                unsigned ah[4] = { fu(aw[mf][0].x), fu(aw[mf][1].x),
                                   fu(aw[mf][2].x), fu(aw[mf][3].x) };
                unsigned al[4] = { fu(aw[mf][0].y), fu(aw[mf][1].y),
                                   fu(aw[mf][2].y), fu(aw[mf][3].y) };
                #pragma unroll
                for (int nf = 0; nf < NF; ++nf) {
                    mma8(acc[mf][nf], ah, bh[nf]);
                    mma8(acc[mf][nf], al, bh[nf]);
                }
            }
        }
    }

    if (RM) {
        // ---- D=1: direct fragment stores; m (=v) is y's fast axis -> full sectors
        #pragma unroll
        for (int mf = 0; mf < MF; ++mf)
            #pragma unroll
            for (int nf = 0; nf < NF; ++nf) {
                int m = v0 + mb0 + mf * 16 + g;
                int n = b0 + nb0 + nf * 8 + 2 * tg;
                y[(size_t)n * FEAT + XO + m]           = acc[mf][nf][0];
                y[(size_t)(n + 1) * FEAT + XO + m]     = acc[mf][nf][1];
                y[(size_t)n * FEAT + XO + m + 8]       = acc[mf][nf][2];
                y[(size_t)(n + 1) * FEAT + XO + m + 8] = acc[mf][nf][3];
            }
    } else {
        // ---- D>1: stage through smem, write coalesced float4
        __syncthreads();
        #pragma unroll
        for (int mf = 0; mf < MF; ++mf)
            #pragma unroll
            for (int nf = 0; nf < NF; ++nf) {
                int mb = mb0 + mf * 16, nn = nb0 + nf * 8 + 2 * tg;
                S[(mb + g) * SN + nn]         = acc[mf][nf][0];
                S[(mb + g) * SN + nn + 1]     = acc[mf][nf][1];
                S[(mb + g + 8) * SN + nn]     = acc[mf][nf][2];
                S[(mb + g + 8) * SN + nn + 1] = acc[mf][nf][3];
            }
        __syncthreads();

        constexpr int ROW = MCTA * D;
        #pragma unroll
        for (int t = 0; t < NB * ROW / 4 / NT; ++t) {
            int f4 = (tid + t * NT) * 4;
            int bl = f4 / ROW, r = f4 % ROW;
            float4 o;
            o.x = S[((r + 0) / D) * SN + bl * D + (r + 0) % D];
            o.y = S[((r + 1) / D) * SN + bl * D + (r + 1) % D];
            o.z = S[((r + 2) / D) * SN + bl * D + (r + 2) % D];
            o.w = S[((r + 3) / D) * SN + bl * D + (r + 3) % D];
            *(float4*)(y + (size_t)(b0 + bl) * FEAT + XO + v0 * D + r) = o;
        }
    }
}

extern "C" void kernel_launch(void* const* d_in, const int* in_sizes, int n_in,
                              void* d_out, int out_size) {
    const float* x = (const float*)d_in[0];
    const float* w = (const float*)d_in[1];
    float* y = (float*)d_out;
    (void)in_sizes; (void)n_in; (void)out_size;

    wsplit_kernel<<<(W_DIM + NT - 1) / NT, NT>>>(w);

    //        MUL  D   XO    WO   MCTA  NB  KC WM WN
    eqlin_mma<256, 1,   0,     0, 128, 128, 16, 4, 2>
        <<<dim3(BATCH_N / 128, 2), NT>>>(x, y);
    eqlin_mma<128, 3, 256, 65536,  64,  32, 32, 2, 4>
        <<<dim3(BATCH_N / 32, 2), NT>>>(x, y);
    eqlin_mma< 64, 5, 640, 81920,  64,  32, 32, 2, 4>
        <<<dim3(BATCH_N / 32, 1), NT>>>(x, y);
    eqlin_mma< 32, 7, 960, 86016,  32,  32, 32, 2, 4>
        <<<dim3(BATCH_N / 32, 1), NT>>>(x, y);
}

// round 6
// speedup vs baseline: 1.6446x; 1.0720x over previous
#include <cuda_runtime.h>
#include <cuda_bf16.h>
#include <stdint.h>

// Equivariant linear via block-diagonal GEMMs, bf16 3-term emulation on
// m16n8k16 tensor cores with ldmatrix fragment loads.
// Blocks (mul, d, x_off, w_off):
//   (256,1,0,0) (128,3,256,65536) (64,5,640,81920) (32,7,960,86016)
// y[b, XO+v*D+i] = (1/sqrt(MUL)) * sum_u w[WO+v*MUL+u] * x[b, XO+u*D+i]
// GEMM per block: M=MUL (v), K=MUL (u), N=BATCH*D (n=b*D+i).
// w pre-split to bf16 (hi,lo) globals, pre-scaled; x split on the fly.
// acc += wh*xh + wl*xh + wh*xl   (dropped wl*xl ~ 2^-18).

#define FEAT 1184
#define BATCH_N 131072
#define NT 256
#define W_DIM 87040

__device__ __nv_bfloat16 g_wh[W_DIM];
__device__ __nv_bfloat16 g_wl[W_DIM];

__device__ __forceinline__ void cp16(uint32_t saddr, const void* gaddr) {
    asm volatile("cp.async.ca.shared.global [%0], [%1], 16;" :: "r"(saddr), "l"(gaddr));
}
__device__ __forceinline__ void ldsm4(unsigned* r, uint32_t a) {
    asm volatile("ldmatrix.sync.aligned.m8n8.x4.shared.b16 {%0,%1,%2,%3}, [%4];"
        : "=r"(r[0]), "=r"(r[1]), "=r"(r[2]), "=r"(r[3]) : "r"(a));
}
__device__ __forceinline__ void ldsm2(unsigned* r, uint32_t a) {
    asm volatile("ldmatrix.sync.aligned.m8n8.x2.shared.b16 {%0,%1}, [%2];"
        : "=r"(r[0]), "=r"(r[1]) : "r"(a));
}
__device__ __forceinline__ void ldsm2t(unsigned* r, uint32_t a) {
    asm volatile("ldmatrix.sync.aligned.m8n8.x2.trans.shared.b16 {%0,%1}, [%2];"
        : "=r"(r[0]), "=r"(r[1]) : "r"(a));
}
// D += A(16x16) * B(16x8), bf16 in, fp32 accum.
__device__ __forceinline__ void mma16(float* d, const unsigned* a, const unsigned* b) {
    asm volatile("mma.sync.aligned.m16n8k16.row.col.f32.bf16.bf16.f32 "
        "{%0,%1,%2,%3}, {%4,%5,%6,%7}, {%8,%9}, {%0,%1,%2,%3};"
        : "+f"(d[0]), "+f"(d[1]), "+f"(d[2]), "+f"(d[3])
        : "r"(a[0]), "r"(a[1]), "r"(a[2]), "r"(a[3]), "r"(b[0]), "r"(b[1]));
}

__global__ void wsplit_kernel(const float* __restrict__ w) {
    int idx = blockIdx.x * NT + threadIdx.x;
    if (idx >= W_DIM) return;
    float c = (idx < 65536) ? 0.0625f
            : (idx < 81920) ? 0.08838834764831845f
            : (idx < 86016) ? 0.125f
                            : 0.17677669529663687f;
    float v = w[idx] * c;
    __nv_bfloat16 h = __float2bfloat16_rn(v);
    g_wh[idx] = h;
    g_wl[idx] = __float2bfloat16_rn(v - __bfloat162float(h));
}

template<int MUL, int D, int XO, int WO, int MCTA, int NB, int KC, int WM, int WN>
__global__ __launch_bounds__(NT, 2)
void eqlin_bf16(const float* __restrict__ x, float* __restrict__ y)
{
    constexpr int NCOL = NB * D;
    constexpr int NCH  = MUL / KC;
    constexpr int KSh  = KC + 8;             // W (and RM-x) row stride, halves (80B)
    constexpr bool RM  = (D == 1);           // x smem [n][k]; else [k][n]
    constexpr int NS   = NCOL + 8;           // x stride for [k][n] (16B-mult, 80B mod 128)
    constexpr int TMW  = MCTA / WM;
    constexpr int TNW  = NCOL / WN;
    constexpr int MF   = TMW / 16;
    constexpr int NF   = TNW / 8;
    static_assert(TMW % 16 == 0 && TNW % 8 == 0 && WM * WN * 32 == NT, "tiling");
    static_assert(KC % 16 == 0, "kc");

    constexpr int WB = 2 * MCTA * KSh * 2;
    constexpr int XB = 2 * (RM ? NCOL * KSh : KC * NS) * 2;
    constexpr int SN = NCOL + 2;
    constexpr int EPIB = RM ? 0 : MCTA * SN * 4;
    constexpr int SMB = (WB + XB) > EPIB ? (WB + XB) : EPIB;
    static_assert(SMB <= 48 * 1024, "smem");
    constexpr int WSEG = MCTA * (KC / 8);    // 16B segs per W array per stage
    static_assert((2 * WSEG) % NT == 0, "w loader");
    static_assert(RM ? ((NB * KC / 4) % NT == 0) : ((NB * KC) % NT == 0), "x loader");
    static_assert(RM || (NB * MCTA * D) % (4 * NT) == 0, "epilogue");

    __shared__ __align__(16) char smembuf[SMB];
    __nv_bfloat16* whs = (__nv_bfloat16*)smembuf;        // [MCTA][KSh]
    __nv_bfloat16* wls = whs + MCTA * KSh;
    __nv_bfloat16* xhs = wls + MCTA * KSh;               // RM:[NCOL][KSh] else [KC][NS]
    __nv_bfloat16* xls = xhs + (RM ? NCOL * KSh : KC * NS);
    float* S = (float*)smembuf;                          // epilogue (D>1)

    const int tid = threadIdx.x;
    const int b0  = blockIdx.x * NB;
    const int v0  = blockIdx.y * MCTA;
    const int wid = tid >> 5, lane = tid & 31;
    const int g = lane >> 2, tg = lane & 3;
    const int wm = wid % WM, wn = wid / WM;
    const int mb0 = wm * TMW, nb0 = wn * TNW;

    const uint32_t wh_u = (uint32_t)__cvta_generic_to_shared(whs);
    const uint32_t wl_u = (uint32_t)__cvta_generic_to_shared(wls);
    const uint32_t xh_u = (uint32_t)__cvta_generic_to_shared(xhs);
    const uint32_t xl_u = (uint32_t)__cvta_generic_to_shared(xls);

    // ldmatrix lane-derived offsets
    const int m_add = (lane & 7) + 8 * ((lane >> 3) & 1);   // A x4
    const int k_add = 8 * (lane >> 4);
    const int l15 = lane & 15;                              // B x2
    const int bn_l = l15 & 7, bk_l = 8 * (l15 >> 3);        // RM [n][k]
    const int bt_l = (l15 & 7) + 8 * (l15 >> 3);            // trans [k][n]

    float acc[MF][NF][4];
    #pragma unroll
    for (int mf = 0; mf < MF; ++mf)
        #pragma unroll
        for (int nf = 0; nf < NF; ++nf)
            #pragma unroll
            for (int q = 0; q < 4; ++q) acc[mf][nf][q] = 0.f;

    for (int ch = 0; ch < NCH; ++ch) {
        const int u0 = ch * KC;
        __syncthreads();

        // ---- W tiles via cp.async from pre-split bf16 globals
        #pragma unroll
        for (int t = 0; t < 2 * WSEG / NT; ++t) {
            int sid = tid + t * NT;
            int arr = sid / WSEG, r = sid % WSEG;
            int m = r / (KC / 8), s = r % (KC / 8);
            const __nv_bfloat16* gp = (arr ? g_wl : g_wh)
                + (WO + (size_t)(v0 + m) * MUL + u0) + s * 8;
            cp16((arr ? wl_u : wh_u) + (uint32_t)(m * KSh + s * 8) * 2u, gp);
        }
        asm volatile("cp.async.commit_group;");

        // ---- X tile: load f32, split to bf16 hi/lo
        if (RM) {
            #pragma unroll
            for (int t = 0; t < NB * KC / 4 / NT; ++t) {
                int f = tid + t * NT;
                int bl = f / (KC / 4), us = (f % (KC / 4)) * 4;
                const float4 v4 = *(const float4*)(x + (size_t)(b0 + bl) * FEAT
                                                   + XO + u0 + us);
                float vv[4] = {v4.x, v4.y, v4.z, v4.w};
                __nv_bfloat16 h[4], l[4];
                #pragma unroll
                for (int q = 0; q < 4; ++q) {
                    h[q] = __float2bfloat16_rn(vv[q]);
                    l[q] = __float2bfloat16_rn(vv[q] - __bfloat162float(h[q]));
                }
                *(__nv_bfloat162*)(xhs + bl * KSh + us)     = {h[0], h[1]};
                *(__nv_bfloat162*)(xhs + bl * KSh + us + 2) = {h[2], h[3]};
                *(__nv_bfloat162*)(xls + bl * KSh + us)     = {l[0], l[1]};
                *(__nv_bfloat162*)(xls + bl * KSh + us + 2) = {l[2], l[3]};
            }
        } else {
            #pragma unroll
            for (int t = 0; t < NB * KC / NT; ++t) {
                int p = tid + t * NT;
                int bl = p / KC, ul = p % KC;
                const float* gp = x + (size_t)(b0 + bl) * FEAT + XO + (u0 + ul) * D;
                __nv_bfloat16* sph = xhs + ul * NS + bl * D;
                __nv_bfloat16* spl = xls + ul * NS + bl * D;
                #pragma unroll
                for (int i = 0; i < D; ++i) {
                    float v = gp[i];
                    __nv_bfloat16 h = __float2bfloat16_rn(v);
                    sph[i] = h;
                    spl[i] = __float2bfloat16_rn(v - __bfloat162float(h));
                }
            }
        }
        asm volatile("cp.async.wait_group 0;" ::: "memory");
        __syncthreads();

        #pragma unroll
        for (int k16 = 0; k16 < KC / 16; ++k16) {
            const int kk = k16 * 16;
            unsigned ah[MF][4], al[MF][4];
            #pragma unroll
            for (int mf = 0; mf < MF; ++mf) {
                uint32_t off = (uint32_t)((mb0 + mf * 16 + m_add) * KSh
                                          + kk + k_add) * 2u;
                ldsm4(ah[mf], wh_u + off);
                ldsm4(al[mf], wl_u + off);
            }
            #pragma unroll
            for (int nf = 0; nf < NF; ++nf) {
                unsigned bh[2], bl2[2];
                if (RM) {
                    uint32_t off = (uint32_t)((nb0 + nf * 8 + bn_l) * KSh
                                              + kk + bk_l) * 2u;
                    ldsm2(bh, xh_u + off);
                    ldsm2(bl2, xl_u + off);
                } else {
                    uint32_t off = (uint32_t)((kk + bt_l) * NS
                                              + nb0 + nf * 8) * 2u;
                    ldsm2t(bh, xh_u + off);
                    ldsm2t(bl2, xl_u + off);
                }
                #pragma unroll
                for (int mf = 0; mf < MF; ++mf) {
                    mma16(acc[mf][nf], ah[mf], bh);    // wh*xh
                    mma16(acc[mf][nf], al[mf], bh);    // wl*xh
                    mma16(acc[mf][nf], ah[mf], bl2);   // wh*xl
                }
            }
        }
    }

    if (RM) {
        // ---- D=1: direct fragment stores; m (=v) is y's fast axis
        #pragma unroll
        for (int mf = 0; mf < MF; ++mf)
            #pragma unroll
            for (int nf = 0; nf < NF; ++nf) {
                int m = v0 + mb0 + mf * 16 + g;
                int n = b0 + nb0 + nf * 8 + 2 * tg;
                y[(size_t)n * FEAT + XO + m]           = acc[mf][nf][0];
                y[(size_t)(n + 1) * FEAT + XO + m]     = acc[mf][nf][1];
                y[(size_t)n * FEAT + XO + m + 8]       = acc[mf][nf][2];
                y[(size_t)(n + 1) * FEAT + XO + m + 8] = acc[mf][nf][3];
            }
    } else {
        // ---- D>1: stage via smem, write coalesced float4
        __syncthreads();
        #pragma unroll
        for (int mf = 0; mf < MF; ++mf)
            #pragma unroll
            for (int nf = 0; nf < NF; ++nf) {
                int mb = mb0 + mf * 16, nn = nb0 + nf * 8 + 2 * tg;
                S[(mb + g) * SN + nn]         = acc[mf][nf][0];
                S[(mb + g) * SN + nn + 1]     = acc[mf][nf][1];
                S[(mb + g + 8) * SN + nn]     = acc[mf][nf][2];
                S[(mb + g + 8) * SN + nn + 1] = acc[mf][nf][3];
            }
        __syncthreads();

        constexpr int ROW = MCTA * D;
        #pragma unroll
        for (int t = 0; t < NB * ROW / 4 / NT; ++t) {
            int f4 = (tid + t * NT) * 4;
            int bl = f4 / ROW, r = f4 % ROW;
            float4 o;
            o.x = S[((r + 0) / D) * SN + bl * D + (r + 0) % D];
            o.y = S[((r + 1) / D) * SN + bl * D + (r + 1) % D];
            o.z = S[((r + 2) / D) * SN + bl * D + (r + 2) % D];
            o.w = S[((r + 3) / D) * SN + bl * D + (r + 3) % D];
            *(float4*)(y + (size_t)(b0 + bl) * FEAT + XO + v0 * D + r) = o;
        }
    }
}

extern "C" void kernel_launch(void* const* d_in, const int* in_sizes, int n_in,
                              void* d_out, int out_size) {
    const float* x = (const float*)d_in[0];
    const float* w = (const float*)d_in[1];
    float* y = (float*)d_out;
    (void)in_sizes; (void)n_in; (void)out_size;

    wsplit_kernel<<<(W_DIM + NT - 1) / NT, NT>>>(w);

    //          MUL  D   XO    WO   MCTA  NB  KC WM WN
    eqlin_bf16<256, 1,   0,     0, 128, 128, 32, 4, 2>
        <<<dim3(BATCH_N / 128, 2), NT>>>(x, y);
    eqlin_bf16<128, 3, 256, 65536,  64,  32, 32, 2, 4>
        <<<dim3(BATCH_N / 32, 2), NT>>>(x, y);
    eqlin_bf16< 64, 5, 640, 81920,  64,  32, 32, 2, 4>
        <<<dim3(BATCH_N / 32, 1), NT>>>(x, y);
    eqlin_bf16< 32, 7, 960, 86016,  32,  32, 32, 2, 4>
        <<<dim3(BATCH_N / 32, 1), NT>>>(x, y);
}

// round 8
// speedup vs baseline: 1.8454x; 1.1221x over previous
#include <cuda_runtime.h>
#include <cuda_bf16.h>
#include <stdint.h>

// Equivariant linear via block-diagonal GEMMs, bf16 3-term emulation on
// m16n8k16 tensor cores. Fully cp.async 2-stage pipeline:
//   W: pre-split bf16 (hi,lo) globals -> smem (ldmatrix A fragments)
//   x: raw f32 contiguous rows -> smem; hi/lo split done in registers at
//      B-fragment build (cvt.rn.bf16x2.f32; residual via bit-shift bf16->f32).
// acc += wh*xh + wl*xh + wh*xl   (dropped wl*xl ~ 2^-18).
// Blocks (mul, d, x_off, w_off):
//   (256,1,0,0) (128,3,256,65536) (64,5,640,81920) (32,7,960,86016)

#define FEAT 1184
#define BATCH_N 131072
#define NT 256
#define W_DIM 87040

__device__ __nv_bfloat16 g_wh[W_DIM];
__device__ __nv_bfloat16 g_wl[W_DIM];

__device__ __forceinline__ void cp16(uint32_t saddr, const void* gaddr) {
    asm volatile("cp.async.ca.shared.global [%0], [%1], 16;" :: "r"(saddr), "l"(gaddr));
}
__device__ __forceinline__ void ldsm4(unsigned* r, uint32_t a) {
    asm volatile("ldmatrix.sync.aligned.m8n8.x4.shared.b16 {%0,%1,%2,%3}, [%4];"
        : "=r"(r[0]), "=r"(r[1]), "=r"(r[2]), "=r"(r[3]) : "r"(a));
}
__device__ __forceinline__ void mma16(float* d, const unsigned* a, const unsigned* b) {
    asm volatile("mma.sync.aligned.m16n8k16.row.col.f32.bf16.bf16.f32 "
        "{%0,%1,%2,%3}, {%4,%5,%6,%7}, {%8,%9}, {%0,%1,%2,%3};"
        : "+f"(d[0]), "+f"(d[1]), "+f"(d[2]), "+f"(d[3])
        : "r"(a[0]), "r"(a[1]), "r"(a[2]), "r"(a[3]), "r"(b[0]), "r"(b[1]));
}
// pack {hi: cvt(vh), lo: cvt(vl)}
__device__ __forceinline__ unsigned cvt2(float vh, float vl) {
    unsigned r;
    asm("cvt.rn.bf16x2.f32 %0, %1, %2;" : "=r"(r) : "f"(vh), "f"(vl));
    return r;
}
// v0..v3 at ascending k; produce hi-frag and lo-residual frag regs.
__device__ __forceinline__ void split4(float v0, float v1, float v2, float v3,
                                       unsigned* bh, unsigned* bl) {
    bh[0] = cvt2(v1, v0);
    bh[1] = cvt2(v3, v2);
    float h0 = __uint_as_float(bh[0] << 16);
    float h1 = __uint_as_float(bh[0] & 0xffff0000u);
    float h2 = __uint_as_float(bh[1] << 16);
    float h3 = __uint_as_float(bh[1] & 0xffff0000u);
    bl[0] = cvt2(v1 - h1, v0 - h0);
    bl[1] = cvt2(v3 - h3, v2 - h2);
}

__global__ void wsplit_kernel(const float* __restrict__ w) {
    int idx = blockIdx.x * NT + threadIdx.x;
    if (idx >= W_DIM) return;
    float c = (idx < 65536) ? 0.0625f
            : (idx < 81920) ? 0.08838834764831845f
            : (idx < 86016) ? 0.125f
                            : 0.17677669529663687f;
    float v = w[idx] * c;
    __nv_bfloat16 h = __float2bfloat16_rn(v);
    g_wh[idx] = h;
    g_wl[idx] = __float2bfloat16_rn(v - __bfloat162float(h));
}

__host__ __device__ constexpr int csmb(int D, int MCTA, int NB, int KC) {
    int KSh = KC + 8, XRS = KC * D + 4, NCOL = NB * D;
    int SWB = 2 * MCTA * KSh * 2, SXB = NB * XRS * 4;
    int mainb = 2 * SWB + 2 * SXB;
    int epib = (D == 1) ? 0 : MCTA * (NCOL + 2) * 4;
    return mainb > epib ? mainb : epib;
}

template<int MUL, int D, int XO, int WO, int MCTA, int NB, int KC, int WM, int WN,
         int MINB>
__global__ __launch_bounds__(NT, MINB)
void eqlin_pipe(const float* __restrict__ x, float* __restrict__ y)
{
    constexpr int NCOL = NB * D;
    constexpr int NCH  = MUL / KC;
    constexpr int KSh  = KC + 8;               // W smem stride (halves)
    constexpr int XRS  = KC * D + 4;           // x smem row stride (f32, 16B mult)
    constexpr bool RM  = (D == 1);
    constexpr int TMW  = MCTA / WM;
    constexpr int TNW  = NCOL / WN;
    constexpr int MF   = TMW / 16;
    constexpr int NF   = TNW / 8;
    static_assert(TMW % 16 == 0 && TNW % 8 == 0 && WM * WN * 32 == NT, "tiling");
    static_assert(KC % 16 == 0 && NCH >= 2, "kc");

    constexpr int SWB = 2 * MCTA * KSh * 2;    // W bytes per stage (hi+lo)
    constexpr int SXB = NB * XRS * 4;          // x bytes per stage
    constexpr int SMB = csmb(D, MCTA, NB, KC);
    static_assert(SMB <= 48 * 1024, "smem");
    constexpr int WSEG = 2 * MCTA * (KC / 8);  // W 16B segs per stage
    constexpr int XSEG = NB * KC * D / 4;      // x 16B segs per stage
    constexpr int SN   = NCOL + 2;
    static_assert(RM || (NB * MCTA * D) % (4 * NT) == 0, "epilogue");

    extern __shared__ __align__(16) char buf[];
    const uint32_t bu = (uint32_t)__cvta_generic_to_shared(buf);

    const int tid = threadIdx.x;
    const int v0  = blockIdx.x * MCTA;
    const int b0  = blockIdx.y * NB;
    const int wid = tid >> 5, lane = tid & 31;
    const int g = lane >> 2, tg = lane & 3;
    const int wm = wid % WM, wn = wid / WM;
    const int mb0 = wm * TMW, nb0 = wn * TNW;

    const int m_add = (lane & 7) + 8 * ((lane >> 3) & 1);   // ldsm4 row
    const int k_add = 8 * (lane >> 4);

    // per-nf x word offsets (within a stage's x region)
    int xoff[NF];
    #pragma unroll
    for (int nf = 0; nf < NF; ++nf) {
        int n = nb0 + nf * 8 + g;
        xoff[nf] = RM ? n * XRS : (n / D) * XRS + (n % D);
    }

    float acc[MF][NF][4];
    #pragma unroll
    for (int mf = 0; mf < MF; ++mf)
        #pragma unroll
        for (int nf = 0; nf < NF; ++nf)
            #pragma unroll
            for (int q = 0; q < 4; ++q) acc[mf][nf][q] = 0.f;

    auto load_stage = [&](int s, int ch) {
        const int u0 = ch * KC;
        const uint32_t wdst = bu + s * SWB;
        constexpr int WIT = (WSEG + NT - 1) / NT;
        #pragma unroll
        for (int t = 0; t < WIT; ++t) {
            int sid = tid + t * NT;
            if (WSEG % NT == 0 || sid < WSEG) {
                int arr = sid / (WSEG / 2), r = sid % (WSEG / 2);
                int m = r / (KC / 8), sg = r % (KC / 8);
                const __nv_bfloat16* gp = (arr ? g_wl : g_wh)
                    + WO + (size_t)(v0 + m) * MUL + u0 + sg * 8;
                cp16(wdst + (uint32_t)(arr * MCTA * KSh + m * KSh + sg * 8) * 2u, gp);
            }
        }
        const uint32_t xdst = bu + 2 * SWB + s * SXB;
        constexpr int XIT = (XSEG + NT - 1) / NT;
        #pragma unroll
        for (int t = 0; t < XIT; ++t) {
            int sid = tid + t * NT;
            if (XSEG % NT == 0 || sid < XSEG) {
                int bl = sid / (KC * D / 4), sg = sid % (KC * D / 4);
                const float* gp = x + (size_t)(b0 + bl) * FEAT + XO + u0 * D + sg * 4;
                cp16(xdst + (uint32_t)(bl * XRS + sg * 4) * 4u, gp);
            }
        }
        asm volatile("cp.async.commit_group;");
    };

    load_stage(0, 0);

    for (int ch = 0; ch < NCH; ++ch) {
        const int s = ch & 1;
        if (ch + 1 < NCH) {
            load_stage(s ^ 1, ch + 1);
            asm volatile("cp.async.wait_group 1;" ::: "memory");
        } else {
            asm volatile("cp.async.wait_group 0;" ::: "memory");
        }
        __syncthreads();

        const uint32_t whu = bu + s * SWB;
        const uint32_t wlu = whu + (uint32_t)MCTA * KSh * 2u;
        const float* xp = (const float*)(buf + 2 * SWB + s * SXB);

        #pragma unroll
        for (int k16 = 0; k16 < KC / 16; ++k16) {
            const int kk = k16 * 16;
            unsigned ah[MF][4], al[MF][4];
            #pragma unroll
            for (int mf = 0; mf < MF; ++mf) {
                uint32_t off = (uint32_t)((mb0 + mf * 16 + m_add) * KSh
                                          + kk + k_add) * 2u;
                ldsm4(ah[mf], whu + off);
                ldsm4(al[mf], wlu + off);
            }
            #pragma unroll
            for (int nf = 0; nf < NF; ++nf) {
                unsigned bh[2], bl2[2];
                if (RM) {
                    const float* p = xp + xoff[nf] + kk + 2 * tg;
                    float2 a01 = *(const float2*)p;
                    float2 a23 = *(const float2*)(p + 8);
                    split4(a01.x, a01.y, a23.x, a23.y, bh, bl2);
                } else {
                    const float* p = xp + xoff[nf] + (kk + 2 * tg) * D;
                    split4(p[0], p[D], p[8 * D], p[9 * D], bh, bl2);
                }
                #pragma unroll
                for (int mf = 0; mf < MF; ++mf) {
                    mma16(acc[mf][nf], ah[mf], bh);
                    mma16(acc[mf][nf], al[mf], bh);
                    mma16(acc[mf][nf], ah[mf], bl2);
                }
            }
        }
        __syncthreads();
    }

    if (RM) {
        // D=1: direct fragment stores; m (=v) is y's fast axis
        #pragma unroll
        for (int mf = 0; mf < MF; ++mf)
            #pragma unroll
            for (int nf = 0; nf < NF; ++nf) {
                int m = v0 + mb0 + mf * 16 + g;
                int n = b0 + nb0 + nf * 8 + 2 * tg;
                y[(size_t)n * FEAT + XO + m]           = acc[mf][nf][0];
                y[(size_t)(n + 1) * FEAT + XO + m]     = acc[mf][nf][1];
                y[(size_t)n * FEAT + XO + m + 8]       = acc[mf][nf][2];
                y[(size_t)(n + 1) * FEAT + XO + m + 8] = acc[mf][nf][3];
            }
    } else {
        // D>1: stage via smem, write coalesced float4
        float* S = (float*)buf;
        #pragma unroll
        for (int mf = 0; mf < MF; ++mf)
            #pragma unroll
            for (int nf = 0; nf < NF; ++nf) {
                int mb = mb0 + mf * 16, nn = nb0 + nf * 8 + 2 * tg;
                S[(mb + g) * SN + nn]         = acc[mf][nf][0];
                S[(mb + g) * SN + nn + 1]     = acc[mf][nf][1];
                S[(mb + g + 8) * SN + nn]     = acc[mf][nf][2];
                S[(mb + g + 8) * SN + nn + 1] = acc[mf][nf][3];
            }
        __syncthreads();

        constexpr int ROW = MCTA * D;
        #pragma unroll
        for (int t = 0; t < NB * ROW / 4 / NT; ++t) {
            int f4 = (tid + t * NT) * 4;
            int bl = f4 / ROW, r = f4 % ROW;
            float4 o;
            o.x = S[((r + 0) / D) * SN + bl * D + (r + 0) % D];
            o.y = S[((r + 1) / D) * SN + bl * D + (r + 1) % D];
            o.z = S[((r + 2) / D) * SN + bl * D + (r + 2) % D];
            o.w = S[((r + 3) / D) * SN + bl * D + (r + 3) % D];
            *(float4*)(y + (size_t)(b0 + bl) * FEAT + XO + v0 * D + r) = o;
        }
    }
}

extern "C" void kernel_launch(void* const* d_in, const int* in_sizes, int n_in,
                              void* d_out, int out_size) {
    const float* x = (const float*)d_in[0];
    const float* w = (const float*)d_in[1];
    float* y = (float*)d_out;
    (void)in_sizes; (void)n_in; (void)out_size;

    wsplit_kernel<<<(W_DIM + NT - 1) / NT, NT>>>(w);

    //          MUL  D   XO    WO   MCTA NB  KC WM WN MINB    grid(v-tiles, batch-tiles)
    eqlin_pipe<256, 1,   0,     0,  64, 64, 32, 2, 4, 2>
        <<<dim3(4, BATCH_N / 64), NT, csmb(1, 64, 64, 32)>>>(x, y);
    eqlin_pipe<128, 3, 256, 65536,  64, 32, 32, 2, 4, 2>
        <<<dim3(2, BATCH_N / 32), NT, csmb(3, 64, 32, 32)>>>(x, y);
    eqlin_pipe< 64, 5, 640, 81920,  64, 16, 32, 4, 2, 3>
        <<<dim3(1, BATCH_N / 16), NT, csmb(5, 64, 16, 32)>>>(x, y);
    eqlin_pipe< 32, 7, 960, 86016,  32, 32, 16, 2, 4, 3>
        <<<dim3(1, BATCH_N / 32), NT, csmb(7, 32, 32, 16)>>>(x, y);
}